// round 5
// baseline (speedup 1.0000x reference)
#include <cuda_runtime.h>
#include <cuda_bf16.h>
#include <cstdint>
#include <cstddef>

// Problem constants (fixed shapes per reference: B=16, N=8192, C=256, M=2048)
#define NB   16
#define NP   8192
#define NC   256
#define MS   2048
#define TPB  512
#define PPT  (NP / TPB)      // 16 points per thread
#define NW   (TPB / 32)      // 16 warps

// Scratch for selected indices (device global: no allocation allowed)
__device__ int g_idx[NB * MS];

// ---------------------------------------------------------------------------
// FPS kernel: one CTA per batch. Points + running min-dist live in registers;
// shared memory holds a copy of the points only for the per-iteration
// broadcast fetch of the selected point's coordinates.
// ---------------------------------------------------------------------------
__global__ __launch_bounds__(TPB, 1)
void fps_kernel(const float* __restrict__ pts)
{
    extern __shared__ float sm[];           // sx[NP], sy[NP], sz[NP] = 96 KB
    float* sx = sm;
    float* sy = sm + NP;
    float* sz = sm + 2 * NP;

    __shared__ float  s_wv[NW];
    __shared__ int    s_wi[NW];
    __shared__ int    s_far;
    __shared__ double s_ax[NW], s_ay[NW], s_az[NW];

    const int t    = threadIdx.x;
    const int b    = blockIdx.x;
    const int lane = t & 31;
    const int warp = t >> 5;

    const float* base = pts + (size_t)b * 3 * NP;

    // Stage points into shared memory (coalesced; input layout is [3, N])
    for (int i = t; i < NP; i += TPB) {
        sx[i] = base[i];
        sy[i] = base[NP + i];
        sz[i] = base[2 * NP + i];
    }
    __syncthreads();

    // Register-resident copy (strided mapping i = t + k*TPB: conflict-free)
    float x[PPT], y[PPT], z[PPT], dist[PPT];
#pragma unroll
    for (int k = 0; k < PPT; k++) {
        int i = t + k * TPB;
        x[k] = sx[i];
        y[k] = sy[i];
        z[k] = sz[i];
        dist[k] = 1e10f;
    }

    // ---- Centroid (double accumulation; d0 top-gap >> rounding noise) ----
    double ax = 0.0, ay = 0.0, az = 0.0;
#pragma unroll
    for (int k = 0; k < PPT; k++) {
        ax += (double)x[k];
        ay += (double)y[k];
        az += (double)z[k];
    }
#pragma unroll
    for (int o = 16; o > 0; o >>= 1) {
        ax += __shfl_down_sync(0xffffffffu, ax, o);
        ay += __shfl_down_sync(0xffffffffu, ay, o);
        az += __shfl_down_sync(0xffffffffu, az, o);
    }
    if (lane == 0) { s_ax[warp] = ax; s_ay[warp] = ay; s_az[warp] = az; }
    __syncthreads();
    if (warp == 0) {
        ax = (lane < NW) ? s_ax[lane] : 0.0;
        ay = (lane < NW) ? s_ay[lane] : 0.0;
        az = (lane < NW) ? s_az[lane] : 0.0;
#pragma unroll
        for (int o = 8; o > 0; o >>= 1) {
            ax += __shfl_down_sync(0xffffffffu, ax, o);
            ay += __shfl_down_sync(0xffffffffu, ay, o);
            az += __shfl_down_sync(0xffffffffu, az, o);
        }
        if (lane == 0) { s_ax[0] = ax; s_ay[0] = ay; s_az[0] = az; }
    }
    __syncthreads();
    const float cx0 = (float)(s_ax[0] / (double)NP);
    const float cy0 = (float)(s_ay[0] / (double)NP);
    const float cz0 = (float)(s_az[0] / (double)NP);

    // ---- Initial farthest = argmax of dist-to-centroid (first-index ties) --
    float bv = -1e30f;
    int   bi = 0;
#pragma unroll
    for (int k = 0; k < PPT; k++) {
        float dx = x[k] - cx0;
        float dy = y[k] - cy0;
        float dz = z[k] - cz0;
        float d  = fmaf(dz, dz, fmaf(dy, dy, dx * dx));
        if (d > bv) { bv = d; bi = t + k * TPB; }   // ascending i => strict >
    }
#pragma unroll
    for (int o = 16; o > 0; o >>= 1) {
        float ov = __shfl_down_sync(0xffffffffu, bv, o);
        int   oi = __shfl_down_sync(0xffffffffu, bi, o);
        if (ov > bv || (ov == bv && oi < bi)) { bv = ov; bi = oi; }
    }
    if (lane == 0) { s_wv[warp] = bv; s_wi[warp] = bi; }
    __syncthreads();
    if (warp == 0) {
        bv = (lane < NW) ? s_wv[lane] : -1e30f;
        bi = (lane < NW) ? s_wi[lane] : 0x7fffffff;
#pragma unroll
        for (int o = 8; o > 0; o >>= 1) {
            float ov = __shfl_down_sync(0xffffffffu, bv, o);
            int   oi = __shfl_down_sync(0xffffffffu, bi, o);
            if (ov > bv || (ov == bv && oi < bi)) { bv = ov; bi = oi; }
        }
        if (lane == 0) s_far = bi;
    }
    __syncthreads();

    // ---- Main sequential loop: record idx, update min-dist, argmax --------
    for (int m = 0; m < MS; m++) {
        const int far = s_far;
        if (t == 0) g_idx[b * MS + m] = far;

        const float cx = sx[far];   // broadcast LDS
        const float cy = sy[far];
        const float cz = sz[far];

        bv = -1e30f;
        bi = 0;
#pragma unroll
        for (int k = 0; k < PPT; k++) {
            float dx = x[k] - cx;
            float dy = y[k] - cy;
            float dz = z[k] - cz;
            float d  = fmaf(dz, dz, fmaf(dy, dy, dx * dx));
            float nd = fminf(dist[k], d);
            dist[k] = nd;
            if (nd > bv) { bv = nd; bi = t + k * TPB; }
        }

        // warp-level argmax (min index on ties)
#pragma unroll
        for (int o = 16; o > 0; o >>= 1) {
            float ov = __shfl_down_sync(0xffffffffu, bv, o);
            int   oi = __shfl_down_sync(0xffffffffu, bi, o);
            if (ov > bv || (ov == bv && oi < bi)) { bv = ov; bi = oi; }
        }
        if (lane == 0) { s_wv[warp] = bv; s_wi[warp] = bi; }
        __syncthreads();
        if (warp == 0) {
            bv = (lane < NW) ? s_wv[lane] : -1e30f;
            bi = (lane < NW) ? s_wi[lane] : 0x7fffffff;
#pragma unroll
            for (int o = 8; o > 0; o >>= 1) {
                float ov = __shfl_down_sync(0xffffffffu, bv, o);
                int   oi = __shfl_down_sync(0xffffffffu, bi, o);
                if (ov > bv || (ov == bv && oi < bi)) { bv = ov; bi = oi; }
            }
            if (lane == 0) s_far = bi;
        }
        __syncthreads();
    }
}

// ---------------------------------------------------------------------------
// Gather sampled points: out[0 .. B*M*3) = pts[b, d, idx[b,m]]
// ---------------------------------------------------------------------------
__global__ void gather_points_kernel(const float* __restrict__ pts,
                                     float* __restrict__ out)
{
    int g = blockIdx.x * blockDim.x + threadIdx.x;
    if (g >= NB * MS * 3) return;
    int d = g % 3;
    int m = (g / 3) % MS;
    int b = g / (3 * MS);
    int i = g_idx[b * MS + m];
    out[g] = pts[((size_t)b * 3 + d) * NP + i];
}

// ---------------------------------------------------------------------------
// Gather sampled features: out[B*M*3 + (b,m,c)] = feats[b, c, idx[b,m]]
// Coalesced float4 writes; reads are inherently scattered (random idx).
// ---------------------------------------------------------------------------
__global__ void gather_feats_kernel(const float* __restrict__ feats,
                                    float* __restrict__ out)
{
    const int C4 = NC / 4;                             // 64
    int g = blockIdx.x * blockDim.x + threadIdx.x;     // B*M*C4 total
    int c4 = g % C4;
    int m  = (g / C4) % MS;
    int b  = g / (C4 * MS);
    int i  = g_idx[b * MS + m];

    const float* f = feats + ((size_t)b * NC + (size_t)c4 * 4) * NP + i;
    float4 v;
    v.x = f[0];
    v.y = f[NP];
    v.z = f[2 * NP];
    v.w = f[3 * NP];
    reinterpret_cast<float4*>(out)[(NB * MS * 3) / 4 + g] = v;
}

// ---------------------------------------------------------------------------
extern "C" void kernel_launch(void* const* d_in, const int* in_sizes, int n_in,
                              void* d_out, int out_size)
{
    const float* pts   = (const float*)d_in[0];   // [B, 3, N]
    const float* feats = (const float*)d_in[1];   // [B, C, N]
    float* out = (float*)d_out;                   // [B*M*3] ++ [B*M*C]

    const size_t smem_bytes = (size_t)3 * NP * sizeof(float);   // 96 KB
    cudaFuncSetAttribute(fps_kernel,
                         cudaFuncAttributeMaxDynamicSharedMemorySize,
                         (int)smem_bytes);

    fps_kernel<<<NB, TPB, smem_bytes>>>(pts);

    gather_points_kernel<<<(NB * MS * 3 + 255) / 256, 256>>>(pts, out);

    const int feat_threads = NB * MS * (NC / 4);   // 2,097,152
    gather_feats_kernel<<<feat_threads / 256, 256>>>(feats, out);
}

// round 8
// speedup vs baseline: 1.0298x; 1.0298x over previous
#include <cuda_runtime.h>
#include <cuda_bf16.h>
#include <cstdint>
#include <cstddef>

// Fixed shapes per reference: B=16, N=8192, C=256, M=2048
#define NB    16
#define NP    8192
#define NC    256
#define MS    2048
#define TPB   512
#define PPT   (NP / TPB)       // 16 points per thread
#define NPAIR (PPT / 2)        // 8 packed pairs per thread
#define NW    (TPB / 32)       // 16 warps

// Scratch for selected indices (device global: no allocation allowed)
__device__ int g_idx[NB * MS];

// ---- packed f32x2 helpers (Blackwell FFMA2 path; bit-exact per lane) ------
__device__ __forceinline__ unsigned long long pk2(float lo, float hi) {
    unsigned long long r;
    asm("mov.b64 %0, {%1, %2};" : "=l"(r) : "f"(lo), "f"(hi));
    return r;
}
__device__ __forceinline__ void up2(unsigned long long v, float& lo, float& hi) {
    asm("mov.b64 {%0, %1}, %2;" : "=f"(lo), "=f"(hi) : "l"(v));
}
__device__ __forceinline__ unsigned long long add2(unsigned long long a,
                                                   unsigned long long b) {
    unsigned long long r;
    asm("add.rn.f32x2 %0, %1, %2;" : "=l"(r) : "l"(a), "l"(b));
    return r;
}
__device__ __forceinline__ unsigned long long mul2(unsigned long long a,
                                                   unsigned long long b) {
    unsigned long long r;
    asm("mul.rn.f32x2 %0, %1, %2;" : "=l"(r) : "l"(a), "l"(b));
    return r;
}
__device__ __forceinline__ unsigned long long fma2(unsigned long long a,
                                                   unsigned long long b,
                                                   unsigned long long c) {
    unsigned long long r;
    asm("fma.rn.f32x2 %0, %1, %2, %3;" : "=l"(r) : "l"(a), "l"(b), "l"(c));
    return r;
}

// Packed argmax key: dist >= 0 so float bits order == value order.
// key = (bits << 13) | (8191 - idx): max key => max value, min index on ties.
__device__ __forceinline__ unsigned long long make_key(float v, int idx) {
    return ((unsigned long long)__float_as_uint(v) << 13)
         | (unsigned long long)(8191 - idx);
}

// ---------------------------------------------------------------------------
// FPS: one CTA per batch. Points + min-dist register-resident. One barrier
// per iteration via rotating 64-bit atomicMax key buffers.
// ---------------------------------------------------------------------------
__global__ __launch_bounds__(TPB, 1)
void fps_kernel(const float* __restrict__ pts)
{
    extern __shared__ float sm[];           // sx[NP], sy[NP], sz[NP] = 96 KB
    float* sx = sm;
    float* sy = sm + NP;
    float* sz = sm + 2 * NP;

    __shared__ unsigned long long s_key[3];
    __shared__ double s_ax[NW], s_ay[NW], s_az[NW];

    const int t    = threadIdx.x;
    const int b    = blockIdx.x;
    const int lane = t & 31;
    const int warp = t >> 5;

    const float* base = pts + (size_t)b * 3 * NP;

    if (t < 3) s_key[t] = 0ULL;

    // Stage points into shared memory (coalesced; input layout [3, N])
    for (int i = t; i < NP; i += TPB) {
        sx[i] = base[i];
        sy[i] = base[NP + i];
        sz[i] = base[2 * NP + i];
    }
    __syncthreads();

    // Register-resident packed copy: pair (2j, 2j+1) -> indices t+2j*TPB, t+(2j+1)*TPB
    unsigned long long x2[NPAIR], y2[NPAIR], z2[NPAIR];
    float dist[PPT];
#pragma unroll
    for (int j = 0; j < NPAIR; j++) {
        int i0 = t + (2 * j) * TPB;
        int i1 = i0 + TPB;
        x2[j] = pk2(sx[i0], sx[i1]);
        y2[j] = pk2(sy[i0], sy[i1]);
        z2[j] = pk2(sz[i0], sz[i1]);
        dist[2 * j]     = 1e10f;
        dist[2 * j + 1] = 1e10f;
    }

    // ---- Centroid (double accumulation; runs once) -------------------------
    double ax = 0.0, ay = 0.0, az = 0.0;
#pragma unroll
    for (int j = 0; j < NPAIR; j++) {
        float a0, a1;
        up2(x2[j], a0, a1); ax += (double)a0 + (double)a1;
        up2(y2[j], a0, a1); ay += (double)a0 + (double)a1;
        up2(z2[j], a0, a1); az += (double)a0 + (double)a1;
    }
#pragma unroll
    for (int o = 16; o > 0; o >>= 1) {
        ax += __shfl_down_sync(0xffffffffu, ax, o);
        ay += __shfl_down_sync(0xffffffffu, ay, o);
        az += __shfl_down_sync(0xffffffffu, az, o);
    }
    if (lane == 0) { s_ax[warp] = ax; s_ay[warp] = ay; s_az[warp] = az; }
    __syncthreads();
    if (warp == 0) {
        ax = (lane < NW) ? s_ax[lane] : 0.0;
        ay = (lane < NW) ? s_ay[lane] : 0.0;
        az = (lane < NW) ? s_az[lane] : 0.0;
#pragma unroll
        for (int o = 8; o > 0; o >>= 1) {
            ax += __shfl_down_sync(0xffffffffu, ax, o);
            ay += __shfl_down_sync(0xffffffffu, ay, o);
            az += __shfl_down_sync(0xffffffffu, az, o);
        }
        if (lane == 0) { s_ax[0] = ax; s_ay[0] = ay; s_az[0] = az; }
    }
    __syncthreads();
    const float cx0 = (float)(s_ax[0] / (double)NP);
    const float cy0 = (float)(s_ay[0] / (double)NP);
    const float cz0 = (float)(s_az[0] / (double)NP);

    // ---- Initial farthest = argmax dist-to-centroid (first-index ties) -----
    {
        const unsigned long long ncx = pk2(-cx0, -cx0);
        const unsigned long long ncy = pk2(-cy0, -cy0);
        const unsigned long long ncz = pk2(-cz0, -cz0);
        float bv = -1e30f;
        int   bi = 0;
#pragma unroll
        for (int j = 0; j < NPAIR; j++) {
            unsigned long long dx = add2(x2[j], ncx);
            unsigned long long dy = add2(y2[j], ncy);
            unsigned long long dz = add2(z2[j], ncz);
            unsigned long long d  = mul2(dx, dx);
            d = fma2(dy, dy, d);
            d = fma2(dz, dz, d);
            float d0, d1;
            up2(d, d0, d1);
            int i0 = t + (2 * j) * TPB;
            if (d0 > bv) { bv = d0; bi = i0; }         // ascending idx => strict >
            if (d1 > bv) { bv = d1; bi = i0 + TPB; }
        }
        float wv = bv;
#pragma unroll
        for (int o = 16; o > 0; o >>= 1)
            wv = fmaxf(wv, __shfl_xor_sync(0xffffffffu, wv, o));
        int cand = (bv == wv) ? bi : 0x7fffffff;
        int mi = __reduce_min_sync(0xffffffffu, cand);
        if (lane == 0) atomicMax(&s_key[2], make_key(wv, mi));
        __syncthreads();
    }
    unsigned long long keyprev = s_key[2];

    // ---- Main sequential loop: ONE barrier per iteration --------------------
    // iter m: reads keyprev (buf written last iter), atomics into buf[m%3],
    // resets buf[(m+1)%3] (last read two barriers ago -> safe).
    for (int m = 0; m < MS; m++) {
        const int far = 8191 - (int)(keyprev & 8191ULL);
        if (t == 0) {
            g_idx[b * MS + m] = far;
            s_key[(m + 1) % 3] = 0ULL;
        }

        const float cx = sx[far];   // broadcast LDS
        const float cy = sy[far];
        const float cz = sz[far];
        const unsigned long long ncx = pk2(-cx, -cx);
        const unsigned long long ncy = pk2(-cy, -cy);
        const unsigned long long ncz = pk2(-cz, -cz);

        float bv0 = -1e30f, bv1 = -1e30f;
#pragma unroll
        for (int j = 0; j < NPAIR; j++) {
            unsigned long long dx = add2(x2[j], ncx);   // x + (-c) == x - c exactly
            unsigned long long dy = add2(y2[j], ncy);
            unsigned long long dz = add2(z2[j], ncz);
            unsigned long long d  = mul2(dx, dx);
            d = fma2(dy, dy, d);
            d = fma2(dz, dz, d);
            float d0, d1;
            up2(d, d0, d1);
            float n0 = fminf(dist[2 * j],     d0);
            float n1 = fminf(dist[2 * j + 1], d1);
            dist[2 * j]     = n0;
            dist[2 * j + 1] = n1;
            bv0 = fmaxf(bv0, n0);
            bv1 = fmaxf(bv1, n1);
        }
        const float bv = fmaxf(bv0, bv1);

        // Recover thread-local min index of the max value (descending k =>
        // final write is the smallest matching k; FMNMX preserved bits exactly).
        int bi = 0;
#pragma unroll
        for (int k = PPT - 1; k >= 0; k--)
            if (dist[k] == bv) bi = t + k * TPB;

        // Warp: max value, then min index among ties via one REDUX.MIN
        float wv = bv;
#pragma unroll
        for (int o = 16; o > 0; o >>= 1)
            wv = fmaxf(wv, __shfl_xor_sync(0xffffffffu, wv, o));
        int cand = (bv == wv) ? bi : 0x7fffffff;
        int mi = __reduce_min_sync(0xffffffffu, cand);

        if (lane == 0) atomicMax(&s_key[m % 3], make_key(wv, mi));
        __syncthreads();
        keyprev = s_key[m % 3];
    }
}

// ---------------------------------------------------------------------------
// Gather sampled points: out[0 .. B*M*3) = pts[b, d, idx[b,m]]
// ---------------------------------------------------------------------------
__global__ void gather_points_kernel(const float* __restrict__ pts,
                                     float* __restrict__ out)
{
    int g = blockIdx.x * blockDim.x + threadIdx.x;
    if (g >= NB * MS * 3) return;
    int d = g % 3;
    int m = (g / 3) % MS;
    int b = g / (3 * MS);
    int i = g_idx[b * MS + m];
    out[g] = pts[((size_t)b * 3 + d) * NP + i];
}

// ---------------------------------------------------------------------------
// Gather sampled features: out[B*M*3 + (b,m,c)] = feats[b, c, idx[b,m]]
// Coalesced float4 writes; reads are inherently scattered (random idx).
// ---------------------------------------------------------------------------
__global__ void gather_feats_kernel(const float* __restrict__ feats,
                                    float* __restrict__ out)
{
    const int C4 = NC / 4;                             // 64
    int g = blockIdx.x * blockDim.x + threadIdx.x;     // B*M*C4 total
    int c4 = g % C4;
    int m  = (g / C4) % MS;
    int b  = g / (C4 * MS);
    int i  = g_idx[b * MS + m];

    const float* f = feats + ((size_t)b * NC + (size_t)c4 * 4) * NP + i;
    float4 v;
    v.x = f[0];
    v.y = f[NP];
    v.z = f[2 * NP];
    v.w = f[3 * NP];
    reinterpret_cast<float4*>(out)[(NB * MS * 3) / 4 + g] = v;
}

// ---------------------------------------------------------------------------
extern "C" void kernel_launch(void* const* d_in, const int* in_sizes, int n_in,
                              void* d_out, int out_size)
{
    const float* pts   = (const float*)d_in[0];   // [B, 3, N]
    const float* feats = (const float*)d_in[1];   // [B, C, N]
    float* out = (float*)d_out;                   // [B*M*3] ++ [B*M*C]

    const size_t smem_bytes = (size_t)3 * NP * sizeof(float);   // 96 KB
    cudaFuncSetAttribute(fps_kernel,
                         cudaFuncAttributeMaxDynamicSharedMemorySize,
                         (int)smem_bytes);

    fps_kernel<<<NB, TPB, smem_bytes>>>(pts);

    gather_points_kernel<<<(NB * MS * 3 + 255) / 256, 256>>>(pts, out);

    const int feat_threads = NB * MS * (NC / 4);   // 2,097,152
    gather_feats_kernel<<<feat_threads / 256, 256>>>(feats, out);
}

// round 9
// speedup vs baseline: 1.2726x; 1.2358x over previous
#include <cuda_runtime.h>
#include <cuda_bf16.h>
#include <cstdint>
#include <cstddef>

// Fixed shapes per reference: B=16, N=8192, C=256, M=2048
#define NB    16
#define NP    8192
#define NC    256
#define MS    2048
#define TPB   256
#define PPT   (NP / TPB)       // 32 points per thread
#define NPAIR (PPT / 2)        // 16 packed pairs per thread
#define NW    (TPB / 32)       // 8 warps

// Scratch for selected indices (device global: no allocation allowed)
__device__ int g_idx[NB * MS];

// ---- packed f32x2 helpers (bit-exact per lane vs scalar) ------------------
__device__ __forceinline__ unsigned long long pk2(float lo, float hi) {
    unsigned long long r;
    asm("mov.b64 %0, {%1, %2};" : "=l"(r) : "f"(lo), "f"(hi));
    return r;
}
__device__ __forceinline__ void up2(unsigned long long v, float& lo, float& hi) {
    asm("mov.b64 {%0, %1}, %2;" : "=f"(lo), "=f"(hi) : "l"(v));
}
__device__ __forceinline__ unsigned long long add2(unsigned long long a,
                                                   unsigned long long b) {
    unsigned long long r;
    asm("add.rn.f32x2 %0, %1, %2;" : "=l"(r) : "l"(a), "l"(b));
    return r;
}
__device__ __forceinline__ unsigned long long mul2(unsigned long long a,
                                                   unsigned long long b) {
    unsigned long long r;
    asm("mul.rn.f32x2 %0, %1, %2;" : "=l"(r) : "l"(a), "l"(b));
    return r;
}
__device__ __forceinline__ unsigned long long fma2(unsigned long long a,
                                                   unsigned long long b,
                                                   unsigned long long c) {
    unsigned long long r;
    asm("fma.rn.f32x2 %0, %1, %2, %3;" : "=l"(r) : "l"(a), "l"(b), "l"(c));
    return r;
}

// 64-bit argmax key: dist >= 0 so float bits order == value order.
// key = (bits << 13) | (8191 - idx): max key => max value, min index on ties.
__device__ __forceinline__ unsigned long long make_key(unsigned int vbits, int idx) {
    return ((unsigned long long)vbits << 13)
         | (unsigned long long)(8191 - idx);
}
__device__ __forceinline__ unsigned long long umax64(unsigned long long a,
                                                     unsigned long long b) {
    return a > b ? a : b;
}

// ---------------------------------------------------------------------------
// FPS: one CTA per batch, 8 warps. Points + min-dist register-resident.
// Tail per iter: 2x REDUX (warp) -> STS key[warp] -> ONE barrier ->
// redundant 8-way tree max in every thread. No atomics, no shfl chains.
// ---------------------------------------------------------------------------
__global__ __launch_bounds__(TPB, 1)
void fps_kernel(const float* __restrict__ pts)
{
    extern __shared__ float sm[];           // sx[NP], sy[NP], sz[NP] = 96 KB
    float* sx = sm;
    float* sy = sm + NP;
    float* sz = sm + 2 * NP;

    __shared__ unsigned long long s_key[2][NW];   // double-buffered by parity
    __shared__ double s_ax[NW], s_ay[NW], s_az[NW];

    const int t    = threadIdx.x;
    const int b    = blockIdx.x;
    const int lane = t & 31;
    const int warp = t >> 5;

    const float* base = pts + (size_t)b * 3 * NP;

    // Stage points into shared memory (coalesced; input layout [3, N])
    for (int i = t; i < NP; i += TPB) {
        sx[i] = base[i];
        sy[i] = base[NP + i];
        sz[i] = base[2 * NP + i];
    }
    __syncthreads();

    // Register-resident packed copy: pair (2j,2j+1) -> indices t+2j*TPB, t+(2j+1)*TPB
    unsigned long long x2[NPAIR], y2[NPAIR], z2[NPAIR];
    float dist[PPT];
#pragma unroll
    for (int j = 0; j < NPAIR; j++) {
        int i0 = t + (2 * j) * TPB;
        int i1 = i0 + TPB;
        x2[j] = pk2(sx[i0], sx[i1]);
        y2[j] = pk2(sy[i0], sy[i1]);
        z2[j] = pk2(sz[i0], sz[i1]);
        dist[2 * j]     = 1e10f;
        dist[2 * j + 1] = 1e10f;
    }

    // ---- Centroid (double accumulation; runs once) -------------------------
    double ax = 0.0, ay = 0.0, az = 0.0;
#pragma unroll
    for (int j = 0; j < NPAIR; j++) {
        float a0, a1;
        up2(x2[j], a0, a1); ax += (double)a0 + (double)a1;
        up2(y2[j], a0, a1); ay += (double)a0 + (double)a1;
        up2(z2[j], a0, a1); az += (double)a0 + (double)a1;
    }
#pragma unroll
    for (int o = 16; o > 0; o >>= 1) {
        ax += __shfl_down_sync(0xffffffffu, ax, o);
        ay += __shfl_down_sync(0xffffffffu, ay, o);
        az += __shfl_down_sync(0xffffffffu, az, o);
    }
    if (lane == 0) { s_ax[warp] = ax; s_ay[warp] = ay; s_az[warp] = az; }
    __syncthreads();
    if (warp == 0) {
        ax = (lane < NW) ? s_ax[lane] : 0.0;
        ay = (lane < NW) ? s_ay[lane] : 0.0;
        az = (lane < NW) ? s_az[lane] : 0.0;
#pragma unroll
        for (int o = 4; o > 0; o >>= 1) {
            ax += __shfl_down_sync(0xffffffffu, ax, o);
            ay += __shfl_down_sync(0xffffffffu, ay, o);
            az += __shfl_down_sync(0xffffffffu, az, o);
        }
        if (lane == 0) { s_ax[0] = ax; s_ay[0] = ay; s_az[0] = az; }
    }
    __syncthreads();
    const float cx0 = (float)(s_ax[0] / (double)NP);
    const float cy0 = (float)(s_ay[0] / (double)NP);
    const float cz0 = (float)(s_az[0] / (double)NP);

    // ---- Initial farthest = argmax dist-to-centroid (first-index ties) -----
    unsigned long long keyreg;
    {
        const unsigned long long ncx = pk2(-cx0, -cx0);
        const unsigned long long ncy = pk2(-cy0, -cy0);
        const unsigned long long ncz = pk2(-cz0, -cz0);
        float bv = -1e30f;
        int   bi = 0;
#pragma unroll
        for (int j = 0; j < NPAIR; j++) {
            unsigned long long dx = add2(x2[j], ncx);
            unsigned long long dy = add2(y2[j], ncy);
            unsigned long long dz = add2(z2[j], ncz);
            unsigned long long d  = mul2(dx, dx);
            d = fma2(dy, dy, d);
            d = fma2(dz, dz, d);
            float d0, d1;
            up2(d, d0, d1);
            int i0 = t + (2 * j) * TPB;
            if (d0 > bv) { bv = d0; bi = i0; }        // ascending idx => strict >
            if (d1 > bv) { bv = d1; bi = i0 + TPB; }
        }
        // Note: d0 here can be negative only if fp weirdness; values are squares >= 0.
        unsigned int vb = __float_as_uint(fmaxf(bv, 0.0f));
        // keep exact value for tie test (bv >= 0 in practice; fmaxf is identity)
        unsigned int wv = __reduce_max_sync(0xffffffffu, vb);
        int cand = (vb == wv) ? bi : 0x7fffffff;
        int mi = __reduce_min_sync(0xffffffffu, cand);
        if (lane == 0) s_key[1][warp] = make_key(wv, mi);
        __syncthreads();
        const unsigned long long* k = s_key[1];
        unsigned long long m0 = umax64(k[0], k[1]);
        unsigned long long m1 = umax64(k[2], k[3]);
        unsigned long long m2 = umax64(k[4], k[5]);
        unsigned long long m3 = umax64(k[6], k[7]);
        keyreg = umax64(umax64(m0, m1), umax64(m2, m3));
    }

    // ---- Main sequential loop: ONE barrier, no atomics ---------------------
    for (int m = 0; m < MS; m++) {
        const int par = m & 1;
        const int far = 8191 - (int)(keyreg & 8191ULL);
        if (t == 0) g_idx[b * MS + m] = far;

        const float cx = sx[far];   // broadcast LDS
        const float cy = sy[far];
        const float cz = sz[far];
        const unsigned long long ncx = pk2(-cx, -cx);
        const unsigned long long ncy = pk2(-cy, -cy);
        const unsigned long long ncz = pk2(-cz, -cz);

        float bv0 = -1e30f, bv1 = -1e30f;
#pragma unroll
        for (int j = 0; j < NPAIR; j++) {
            unsigned long long dx = add2(x2[j], ncx);   // x + (-c) == x - c exactly
            unsigned long long dy = add2(y2[j], ncy);
            unsigned long long dz = add2(z2[j], ncz);
            unsigned long long d  = mul2(dx, dx);
            d = fma2(dy, dy, d);
            d = fma2(dz, dz, d);
            float d0, d1;
            up2(d, d0, d1);
            float n0 = fminf(dist[2 * j],     d0);
            float n1 = fminf(dist[2 * j + 1], d1);
            dist[2 * j]     = n0;
            dist[2 * j + 1] = n1;
            bv0 = fmaxf(bv0, n0);
            bv1 = fmaxf(bv1, n1);
        }
        const float bv = fmaxf(bv0, bv1);

        // Recover thread-local min index of the max value (descending k =>
        // final write is the smallest matching k; FMNMX preserves bits exactly).
        int bi = 0;
#pragma unroll
        for (int k = PPT - 1; k >= 0; k--)
            if (dist[k] == bv) bi = t + k * TPB;

        // Warp: single-instruction max on bits (dists >= 0), then min index.
        unsigned int vb = __float_as_uint(bv);
        unsigned int wv = __reduce_max_sync(0xffffffffu, vb);
        int cand = (vb == wv) ? bi : 0x7fffffff;
        int mi = __reduce_min_sync(0xffffffffu, cand);
        if (lane == 0) s_key[par][warp] = make_key(wv, mi);

        __syncthreads();

        // Every thread redundantly reduces the 8 warp keys (broadcast LDS).
        const unsigned long long* k = s_key[par];
        unsigned long long m0 = umax64(k[0], k[1]);
        unsigned long long m1 = umax64(k[2], k[3]);
        unsigned long long m2 = umax64(k[4], k[5]);
        unsigned long long m3 = umax64(k[6], k[7]);
        keyreg = umax64(umax64(m0, m1), umax64(m2, m3));
    }
}

// ---------------------------------------------------------------------------
// Gather sampled points: out[0 .. B*M*3) = pts[b, d, idx[b,m]]
// ---------------------------------------------------------------------------
__global__ void gather_points_kernel(const float* __restrict__ pts,
                                     float* __restrict__ out)
{
    int g = blockIdx.x * blockDim.x + threadIdx.x;
    if (g >= NB * MS * 3) return;
    int d = g % 3;
    int m = (g / 3) % MS;
    int b = g / (3 * MS);
    int i = g_idx[b * MS + m];
    out[g] = pts[((size_t)b * 3 + d) * NP + i];
}

// ---------------------------------------------------------------------------
// Gather sampled features: out[B*M*3 + (b,m,c)] = feats[b, c, idx[b,m]]
// Coalesced float4 writes; reads are inherently scattered (random idx).
// ---------------------------------------------------------------------------
__global__ void gather_feats_kernel(const float* __restrict__ feats,
                                    float* __restrict__ out)
{
    const int C4 = NC / 4;                             // 64
    int g = blockIdx.x * blockDim.x + threadIdx.x;     // B*M*C4 total
    int c4 = g % C4;
    int m  = (g / C4) % MS;
    int b  = g / (C4 * MS);
    int i  = g_idx[b * MS + m];

    const float* f = feats + ((size_t)b * NC + (size_t)c4 * 4) * NP + i;
    float4 v;
    v.x = f[0];
    v.y = f[NP];
    v.z = f[2 * NP];
    v.w = f[3 * NP];
    reinterpret_cast<float4*>(out)[(NB * MS * 3) / 4 + g] = v;
}

// ---------------------------------------------------------------------------
extern "C" void kernel_launch(void* const* d_in, const int* in_sizes, int n_in,
                              void* d_out, int out_size)
{
    const float* pts   = (const float*)d_in[0];   // [B, 3, N]
    const float* feats = (const float*)d_in[1];   // [B, C, N]
    float* out = (float*)d_out;                   // [B*M*3] ++ [B*M*C]

    const size_t smem_bytes = (size_t)3 * NP * sizeof(float);   // 96 KB
    cudaFuncSetAttribute(fps_kernel,
                         cudaFuncAttributeMaxDynamicSharedMemorySize,
                         (int)smem_bytes);

    fps_kernel<<<NB, TPB, smem_bytes>>>(pts);

    gather_points_kernel<<<(NB * MS * 3 + 255) / 256, 256>>>(pts, out);

    const int feat_threads = NB * MS * (NC / 4);   // 2,097,152
    gather_feats_kernel<<<feat_threads / 256, 256>>>(feats, out);
}